// round 17
// baseline (speedup 1.0000x reference)
#include <cuda_runtime.h>
#include <cuda_fp16.h>
#include <cstdint>
#include <math.h>

// ---------------- problem constants ----------------
#define NTOK 4096
#define DDIM 2048
#define HDIM 1408
#define NE   16
#define NS   2
#define NSLOT (NE + NS)
#define TOPK 2
#define TM 128
#define TN 128
#define KC 64
#define MAXROWS (NTOK*TOPK + NE*TM + NTOK*NS)   // 18432
#define MAXTILESM (MAXROWS / TM)                // 144
#define NBN1 (HDIM / TN)     // 11
#define NCH1 (DDIM / KC)     // 32
#define NBN2 (DDIM / TN)     // 16
#define NCH2 (HDIM / KC)     // 22
#define WCH  8192            // chunk elems: 128 x 64 fp16
#define CHU4 1024            // uint4 per chunk

// work queue: [0,1728) = 288 W2-strips (t%6==0) + 1440 P1; [1728,1872) = 144 P1;
// [1872, 4176) = 2304 P2
#define NP1   (MAXTILESM * NBN1)     // 1584
#define NP2   (MAXTILESM * NBN2)     // 2304
#define NW2   (NSLOT * NBN2)         // 288
#define QMIX  (NW2 * 6)              // 1728
#define QP2   (QMIX + (NP1 - NW2*5)) // 1872
#define QTOT  (QP2 + NP2)            // 4176

// smem tile geometry: rows of 64 fp16 (128B) + 16 pad = 144 bytes
#define PITCH 144
#define TILEB (128 * PITCH)          // 18432 B
#define OFF_TOK 0
#define OFF_W   512
#define OFF_ITEM 1024
#define OFF_TILES 1152
#define AOF(b) (OFF_TILES + (b)*2*TILEB)
#define BOF(b) (AOF(b) + TILEB)
#define SMEM_BYTES (OFF_TILES + 4*TILEB)   // 74880

// ---------------- device scratch ----------------
__device__ __align__(16) __half g_w1t[(size_t)NSLOT * NBN1 * NCH1 * WCH];
__device__ __align__(16) __half g_w2t[(size_t)NSLOT * NBN2 * NCH2 * WCH];
__device__ __align__(16) __half g_xc[(size_t)NTOK * DDIM];
__device__ __align__(16) __half g_hid[(size_t)MAXTILESM * NCH2 * WCH];
__device__ int   g_row_token[MAXROWS];
__device__ float g_row_w[MAXROWS];
__device__ int   g_tile_slot[MAXTILESM];
__device__ int   g_topk_i[NTOK * TOPK];
__device__ float g_topk_w[NTOK * TOPK];
__device__ int   g_counts[NE];
__device__ int   g_fill[NE];
__device__ int   g_offsets[NSLOT];
__device__ float g_psum[NE];
__device__ float g_lsum[NE];
__device__ int   g_q;                 // work-queue head
__device__ int   g_done[MAXTILESM];   // per-bm P1 completion count
__device__ int   g_w2rdy[NW2];        // per-(slot,bn) W2 strip readiness

// ---------------- helpers ----------------
__device__ __forceinline__ uint32_t smem_u32(const void* p) {
    uint32_t a;
    asm("{ .reg .u64 t; cvta.to.shared.u64 t, %1; cvt.u32.u64 %0, t; }"
        : "=r"(a) : "l"(p));
    return a;
}
__device__ __forceinline__ void ldsm4(uint32_t* r, uint32_t addr) {
    asm volatile("ldmatrix.sync.aligned.m8n8.x4.shared.b16 {%0,%1,%2,%3}, [%4];"
                 : "=r"(r[0]), "=r"(r[1]), "=r"(r[2]), "=r"(r[3]) : "r"(addr));
}
__device__ __forceinline__ void mmaf16(float* d, const uint32_t* a, const uint32_t* b) {
    asm volatile("mma.sync.aligned.m16n8k16.row.col.f32.f16.f16.f32 "
                 "{%0,%1,%2,%3}, {%4,%5,%6,%7}, {%8,%9}, {%0,%1,%2,%3};"
                 : "+f"(d[0]), "+f"(d[1]), "+f"(d[2]), "+f"(d[3])
                 : "r"(a[0]), "r"(a[1]), "r"(a[2]), "r"(a[3]), "r"(b[0]), "r"(b[1]));
}
__device__ __forceinline__ uint32_t pkh(__half a, __half b) {
    return (uint32_t)__half_as_ushort(a) | ((uint32_t)__half_as_ushort(b) << 16);
}

// ------- W1 transpose + fp16 round into KC=64 tiled layout (standalone) -----
__global__ void conv_w1(const float* __restrict__ ew, const float* __restrict__ sw) {
    const int K = DDIM, N = HDIM;
    int slot = blockIdx.z;
    const float* src = (slot < NE) ? ew + (size_t)slot * K * N
                                   : sw + (size_t)(slot - NE) * K * N;
    __shared__ float t[32][33];
    int k0 = blockIdx.x * 32, n0 = blockIdx.y * 32;
    int tx = threadIdx.x, ty = threadIdx.y;   // 32, 8
#pragma unroll
    for (int i = 0; i < 4; i++)
        t[ty + i * 8][tx] = src[(size_t)(k0 + ty + i * 8) * N + n0 + tx];
    __syncthreads();
    const int k = k0 + tx;
    const int c = k >> 6;
#pragma unroll
    for (int i = 0; i < 4; i++) {
        int n = n0 + ty + i * 8;
        float v = t[tx][ty + i * 8];
        size_t base = ((size_t)(slot * NBN1 + (n >> 7)) * NCH1 + c) * WCH
                      + (size_t)(n & 127) * KC + (k & 63);
        g_w1t[base] = __float2half_rn(v);
    }
}

// ---------------- x fp16 round (linear layout) ----------------
__global__ void conv_x(const float* __restrict__ x) {
    size_t i = ((size_t)blockIdx.x * blockDim.x + threadIdx.x) * 4;
    if (i >= (size_t)NTOK * DDIM) return;
    float4 v = *(const float4*)(x + i);
    __half2 h0 = __floats2half2_rn(v.x, v.y);
    __half2 h1 = __floats2half2_rn(v.z, v.w);
    *(uint2*)(g_xc + i) = make_uint2(*(uint32_t*)&h0, *(uint32_t*)&h1);
}

// ---------------- init ----------------
__global__ void init_kernel(float* __restrict__ out) {
    int idx = blockIdx.x * blockDim.x + threadIdx.x;
    int stride = gridDim.x * blockDim.x;
    for (size_t i = idx; i < (size_t)NTOK * DDIM; i += stride) out[i] = 0.0f;
    for (int i = idx; i < MAXROWS; i += stride) g_row_token[i] = -1;
    if (idx < NE) {
        g_counts[idx] = 0; g_fill[idx] = 0;
        g_psum[idx] = 0.0f; g_lsum[idx] = 0.0f;
    }
    if (idx < MAXTILESM) g_done[idx] = 0;
    if (idx < NW2) g_w2rdy[idx] = 0;
    if (idx == 0) g_q = 0;
}

// ---------------- router ----------------
__global__ void router_kernel(const float* __restrict__ x,
                              const float* __restrict__ gw) {
    int t = blockIdx.x;
    int tid = threadIdx.x;
    float acc[NE];
#pragma unroll
    for (int e = 0; e < NE; e++) acc[e] = 0.0f;
    const float* xr = x + (size_t)t * DDIM;
    for (int d = tid; d < DDIM; d += 128) {
        float xv = xr[d];
        const float* g = gw + d * NE;
#pragma unroll
        for (int e = 0; e < NE; e++) acc[e] += xv * g[e];
    }
    __shared__ float red[128][NE + 1];
#pragma unroll
    for (int e = 0; e < NE; e++) red[tid][e] = acc[e];
    __syncthreads();
    for (int off = 64; off > 0; off >>= 1) {
        if (tid < off) {
#pragma unroll
            for (int e = 0; e < NE; e++) red[tid][e] += red[tid + off][e];
        }
        __syncthreads();
    }
    if (tid == 0) {
        float lg[NE], p[NE];
        float m = -1e30f;
#pragma unroll
        for (int e = 0; e < NE; e++) { lg[e] = red[0][e]; m = fmaxf(m, lg[e]); }
        float s = 0.0f;
#pragma unroll
        for (int e = 0; e < NE; e++) { p[e] = expf(lg[e] - m); s += p[e]; }
        float inv = 1.0f / s;
#pragma unroll
        for (int e = 0; e < NE; e++) p[e] *= inv;
        int i1 = 0;
#pragma unroll
        for (int e = 1; e < NE; e++) if (p[e] > p[i1]) i1 = e;
        int i2 = (i1 == 0) ? 1 : 0;
#pragma unroll
        for (int e = 0; e < NE; e++) if (e != i1 && p[e] > p[i2]) i2 = e;
        float wsum = p[i1] + p[i2];
        g_topk_i[t * 2 + 0] = i1;
        g_topk_i[t * 2 + 1] = i2;
        g_topk_w[t * 2 + 0] = p[i1] / wsum;
        g_topk_w[t * 2 + 1] = p[i2] / wsum;
        atomicAdd(&g_counts[i1], 1);
        atomicAdd(&g_counts[i2], 1);
#pragma unroll
        for (int e = 0; e < NE; e++) {
            atomicAdd(&g_psum[e], p[e]);
            atomicAdd(&g_lsum[e], lg[e]);
        }
    }
}

// ---------------- schedule ----------------
__global__ void schedule_kernel(float* __restrict__ out, long long out_size) {
    if (threadIdx.x != 0 || blockIdx.x != 0) return;
    int tile = 0;
    for (int slot = 0; slot < NSLOT; slot++) {
        int cnt = (slot < NE) ? g_counts[slot] : NTOK;
        g_offsets[slot] = tile * TM;
        int nt = (cnt + TM - 1) / TM;
        for (int i = 0; i < nt; i++) g_tile_slot[tile++] = slot;
    }
    for (; tile < MAXTILESM; tile++) g_tile_slot[tile] = -1;
    float aux = 0.0f;
    for (int e = 0; e < NE; e++)
        aux += (g_psum[e] * (1.0f / NTOK)) * (g_lsum[e] * (1.0f / NTOK));
    aux *= (float)NE;
    if (out_size > (long long)NTOK * DDIM) out[(size_t)NTOK * DDIM] = aux;
}

// ---------------- scatter ----------------
__global__ void scatter_kernel() {
    int i = blockIdx.x * blockDim.x + threadIdx.x;
    const int total = NTOK * TOPK + NTOK * NS;
    if (i >= total) return;
    if (i < NTOK * TOPK) {
        int e = g_topk_i[i];
        int pos = atomicAdd(&g_fill[e], 1);
        int row = g_offsets[e] + pos;
        g_row_token[row] = i >> 1;
        g_row_w[row] = g_topk_w[i];
    } else {
        int j = i - NTOK * TOPK;
        int s = j / NTOK, t = j % NTOK;
        int row = g_offsets[NE + s] + t;
        g_row_token[row] = t;
        g_row_w[row] = 1.0f;
    }
}

// ---------------- W2 strip conversion (inside persistent kernel) ------------
__device__ void w2strip(int id, const float* __restrict__ ew2,
                        const float* __restrict__ sw2, char* smem) {
    const int slot = id / NBN2, bn = id % NBN2;
    const float* src = (slot < NE) ? ew2 + (size_t)slot * HDIM * DDIM
                                   : sw2 + (size_t)(slot - NE) * HDIM * DDIM;
    src += bn * TN;
    float (*tt)[129] = (float(*)[129])(smem + OFF_TILES);
    const int tid = threadIdx.x;
    __half* dstStrip = g_w2t + (size_t)(slot * NBN2 + bn) * NCH2 * WCH;
    for (int kb = 0; kb < HDIM / 32; kb++) {
        const int k0 = kb * 32;
#pragma unroll
        for (int i = 0; i < 16; i++) {
            int u = tid + i * 256;
            int r = u >> 7, cl = u & 127;
            tt[r][cl] = src[(size_t)(k0 + r) * DDIM + cl];
        }
        __syncthreads();
        const int tx = tid & 31, ny = tid >> 5;
        __half* dst = dstStrip + (size_t)(k0 >> 6) * WCH + (k0 & 63) + tx;
#pragma unroll
        for (int i = 0; i < 16; i++) {
            int nloc = ny + i * 8;
            dst[(size_t)nloc * KC] = __float2half_rn(tt[tx][nloc]);
        }
        __syncthreads();
    }
    __threadfence();
    __syncthreads();
    if (tid == 0) *(volatile int*)&g_w2rdy[slot * NBN2 + bn] = 1;
}

// ---------------- one GEMM tile (both phases, runtime flag) ------------------
__device__ void gemm_tile(bool PH1, int bm, int bn, float* __restrict__ out,
                          char* smem) {
    const int slot = g_tile_slot[bm];
    if (!PH1) {
        if (slot < 0) return;
        if (threadIdx.x == 0) {
            while (*(volatile int*)&g_done[bm] < NBN1) __nanosleep(64);
            while (*(volatile int*)&g_w2rdy[slot * NBN2 + bn] == 0) __nanosleep(64);
            __threadfence();
        }
        __syncthreads();
    }
    if (slot >= 0) {
        const int NC = PH1 ? NCH1 : NCH2;
        const int row0 = bm * TM, n0 = bn * TN;
        const int tid = threadIdx.x, wid = tid >> 5, lane = tid & 31;
        int* s_tok = (int*)(smem + OFF_TOK);
        float* s_w = (float*)(smem + OFF_W);
        if (tid < TM) {
            s_tok[tid] = g_row_token[row0 + tid];
            s_w[tid]   = g_row_w[row0 + tid];
        }
        __syncthreads();

        int tDst[4];
#pragma unroll
        for (int i = 0; i < 4; i++) {
            int u = tid + i * 256;
            tDst[i] = (u >> 3) * PITCH + (u & 7) * 16;
        }

        const uint4* srcB = PH1
            ? (const uint4*)g_w1t + (size_t)(slot * NBN1 + bn) * NCH1 * CHU4
            : (const uint4*)g_w2t + (size_t)(slot * NBN2 + bn) * NCH2 * CHU4;
        const uint4* srcA2 = 0;
        const uint4* srcA1 = 0;
        const int ah = tid & 1;
        if (PH1) {
            int tok = s_tok[tid >> 1]; if (tok < 0) tok = 0;
            srcA1 = (const uint4*)(g_xc + (size_t)tok * DDIM) + ah * 4;
        } else {
            srcA2 = (const uint4*)g_hid + (size_t)bm * NCH2 * CHU4;
        }
        const int dA1 = (tid >> 1) * PITCH + ah * 64;

        const uint32_t sb = smem_u32(smem);
        const int warp_m = (wid >> 2) * 64;
        const int warp_n = (wid & 3) * 32;
        const int a_row = warp_m + (lane & 15);
        const int a_c8  = (lane >> 4) << 3;
        const int b_row = warp_n + (lane & 7) + ((lane >> 4) << 3);
        const int b_c8  = lane & 8;

        float acc[4][4][4];
#pragma unroll
        for (int i = 0; i < 4; i++)
#pragma unroll
            for (int j = 0; j < 4; j++)
#pragma unroll
                for (int k = 0; k < 4; k++) acc[i][j][k] = 0.0f;

        // direct load of chunk 0
        if (PH1) {
            char* base = smem + AOF(0) + dA1;
#pragma unroll
            for (int i = 0; i < 4; i++)
                *(uint4*)(base + i * 16) = srcA1[i];
        } else {
#pragma unroll
            for (int i = 0; i < 4; i++)
                *(uint4*)(smem + AOF(0) + tDst[i]) = srcA2[tid + i * 256];
        }
#pragma unroll
        for (int i = 0; i < 4; i++)
            *(uint4*)(smem + BOF(0) + tDst[i]) = srcB[tid + i * 256];
        __syncthreads();

        for (int c = 0; c < NC; c++) {
            const int buf = c & 1;
            const bool have = (c + 1 < NC);

            uint4 sA[4], sB[4];
            if (have) {
                if (PH1) {
                    const uint4* p = srcA1 + (size_t)(c + 1) * 8;
#pragma unroll
                    for (int i = 0; i < 4; i++) sA[i] = p[i];
                } else {
                    const uint4* p = srcA2 + (size_t)(c + 1) * CHU4;
#pragma unroll
                    for (int i = 0; i < 4; i++) sA[i] = p[tid + i * 256];
                }
                const uint4* q = srcB + (size_t)(c + 1) * CHU4;
#pragma unroll
                for (int i = 0; i < 4; i++) sB[i] = q[tid + i * 256];
            }

            {
                const uint32_t ab = sb + AOF(buf);
                const uint32_t bb = sb + BOF(buf);
#pragma unroll
                for (int ks = 0; ks < 4; ks++) {
                    const int kk = ks * 16;
                    const uint32_t baddr = (uint32_t)(b_row * PITCH + (kk + b_c8) * 2);
                    const uint32_t aaddr = (uint32_t)(a_row * PITCH + (kk + a_c8) * 2);
                    uint32_t bh0[4], bh1[4];
                    ldsm4(bh0, bb + baddr);
                    ldsm4(bh1, bb + baddr + 16 * PITCH);
#pragma unroll
                    for (int mi = 0; mi < 4; mi++) {
                        uint32_t af[4];
                        ldsm4(af, ab + aaddr + mi * 16 * PITCH);
                        mmaf16(acc[mi][0], af, bh0); mmaf16(acc[mi][1], af, bh0 + 2);
                        mmaf16(acc[mi][2], af, bh1); mmaf16(acc[mi][3], af, bh1 + 2);
                    }
                }
            }

            if (have) {
                const int nb = (c + 1) & 1;
                if (PH1) {
                    char* base = smem + AOF(nb) + dA1;
#pragma unroll
                    for (int i = 0; i < 4; i++)
                        *(uint4*)(base + i * 16) = sA[i];
                } else {
#pragma unroll
                    for (int i = 0; i < 4; i++)
                        *(uint4*)(smem + AOF(nb) + tDst[i]) = sA[i];
                }
#pragma unroll
                for (int i = 0; i < 4; i++)
                    *(uint4*)(smem + BOF(nb) + tDst[i]) = sB[i];
            }
            __syncthreads();
        }

        // epilogue
        const int gid = lane >> 2, tig = lane & 3;
#pragma unroll
        for (int mi = 0; mi < 4; mi++) {
#pragma unroll
            for (int f = 0; f < 4; f++) {
                const int col = n0 + warp_n + f * 8 + tig * 2;
#pragma unroll
                for (int h = 0; h < 2; h++) {
                    const int r = warp_m + mi * 16 + gid + h * 8;
                    float v0 = acc[mi][f][2 * h];
                    float v1 = acc[mi][f][2 * h + 1];
                    if (PH1) {
                        v0 = v0 / (1.0f + __expf(-v0));
                        v1 = v1 / (1.0f + __expf(-v1));
                        size_t base = ((size_t)bm * NCH2 + (col >> 6)) * WCH
                                      + (size_t)r * KC + (col & 63);
                        *(uint32_t*)(g_hid + base) =
                            pkh(__float2half_rn(v0), __float2half_rn(v1));
                    } else {
                        int tok = s_tok[r];
                        if (tok >= 0) {
                            float w = s_w[r];
                            float* op = out + (size_t)tok * DDIM + col;
                            atomicAdd(op,     w * v0);
                            atomicAdd(op + 1, w * v1);
                        }
                    }
                }
            }
        }
    }
    if (PH1) {
        __threadfence();
        __syncthreads();
        if (threadIdx.x == 0) atomicAdd(&g_done[bm], 1);
    }
}

// ---------------- persistent fused kernel ------------------------------------
__global__ __launch_bounds__(256, 2)
void fused_moe(const float* __restrict__ ew2, const float* __restrict__ sw2,
               float* __restrict__ out) {
    extern __shared__ char smem[];
    int* s_item = (int*)(smem + OFF_ITEM);
    for (;;) {
        __syncthreads();                      // protect smem reuse across items
        if (threadIdx.x == 0) *s_item = atomicAdd(&g_q, 1);
        __syncthreads();
        const int t = *s_item;
        if (t >= QTOT) return;
        if (t < QMIX) {
            if (t % 6 == 0) { w2strip(t / 6, ew2, sw2, smem); continue; }
            const int p = t - (t + 5) / 6;    // P1 index 0..1439
            gemm_tile(true, p / NBN1, p % NBN1, out, smem);
        } else if (t < QP2) {
            const int p = t - NW2;            // P1 index 1440..1583
            gemm_tile(true, p / NBN1, p % NBN1, out, smem);
        } else {
            const int p = t - QP2;            // P2 index 0..2303
            gemm_tile(false, p / NBN2, p % NBN2, out, smem);
        }
    }
}

// ---------------- launch ------------------------------------------------------
extern "C" void kernel_launch(void* const* d_in, const int* in_sizes, int n_in,
                              void* d_out, int out_size) {
    const float* x   = (const float*)d_in[0];
    const float* gw  = (const float*)d_in[1];
    const float* sw1 = (const float*)d_in[2];
    const float* sw2 = (const float*)d_in[3];
    const float* ew1 = (const float*)d_in[4];
    const float* ew2 = (const float*)d_in[5];
    float* out = (float*)d_out;

    static cudaStream_t sA = 0, sC = 0;
    static cudaEvent_t eFork = 0, eA = 0, eC = 0;
    static bool ready = false;
    if (!ready) {
        cudaStreamCreateWithFlags(&sA, cudaStreamNonBlocking);
        cudaStreamCreateWithFlags(&sC, cudaStreamNonBlocking);
        cudaEventCreateWithFlags(&eFork, cudaEventDisableTiming);
        cudaEventCreateWithFlags(&eA, cudaEventDisableTiming);
        cudaEventCreateWithFlags(&eC, cudaEventDisableTiming);
        cudaFuncSetAttribute(fused_moe, cudaFuncAttributeMaxDynamicSharedMemorySize, SMEM_BYTES);
        ready = true;
    }

    dim3 tb(32, 8);

    // fork conversions onto side streams
    cudaEventRecord(eFork, 0);
    cudaStreamWaitEvent(sA, eFork, 0);
    cudaStreamWaitEvent(sC, eFork, 0);
    conv_w1<<<dim3(DDIM / 32, HDIM / 32, NSLOT), tb, 0, sA>>>(ew1, sw1);
    cudaEventRecord(eA, sA);
    conv_x<<<(NTOK * DDIM / 4 + 255) / 256, 256, 0, sC>>>(x);
    cudaEventRecord(eC, sC);

    // main chain on default stream
    init_kernel<<<1024, 256>>>(out);
    router_kernel<<<NTOK, 128>>>(x, gw);
    schedule_kernel<<<1, 32>>>(out, (long long)out_size);
    scatter_kernel<<<(NTOK * (TOPK + NS) + 255) / 256, 256>>>();

    // join conversions, then the single persistent fused kernel
    cudaStreamWaitEvent(0, eA, 0);
    cudaStreamWaitEvent(0, eC, 0);
    fused_moe<<<296, 256, SMEM_BYTES>>>(ew2, sw2, out);
}